// round 1
// baseline (speedup 1.0000x reference)
#include <cuda_runtime.h>
#include <math.h>

#define T_   4
#define B_   32
#define C_   384
#define N_   196
#define H_   12
#define D_   32
#define CN_  (C_*N_)            // 75264
#define BCN  (B_*C_*N_)         // 2408448
#define TBCN (T_*B_*C_*N_)      // 9633792
#define TOKS (T_*B_*N_)         // 25088

// ---------------- scratch (device globals; no allocation allowed) ------------
__device__ float g_qkv[3u * TBCN];     // q,k,v pre-activations -> spikes (in place)
__device__ float g_att[TBCN];          // attention output -> spikes (in place)
__device__ float g_bnscale[3 * C_];
__device__ float g_bnbias[3 * C_];
__device__ float g_pscale[C_];
__device__ float g_pbias[C_];

// ---------------- BN coefficient setup --------------------------------------
__global__ void setup_bn(
    const float* __restrict__ qg, const float* __restrict__ qb, const float* __restrict__ qm, const float* __restrict__ qv,
    const float* __restrict__ kg, const float* __restrict__ kb, const float* __restrict__ km, const float* __restrict__ kv,
    const float* __restrict__ vg, const float* __restrict__ vb, const float* __restrict__ vm, const float* __restrict__ vv,
    const float* __restrict__ pg, const float* __restrict__ pb, const float* __restrict__ pm, const float* __restrict__ pv,
    const float* __restrict__ pbias)
{
    int i = blockIdx.x * blockDim.x + threadIdx.x;
    if (i < 3 * C_) {
        int p = i / C_, c = i - p * C_;
        const float *g, *be, *mu, *va;
        if (p == 0)      { g = qg; be = qb; mu = qm; va = qv; }
        else if (p == 1) { g = kg; be = kb; mu = km; va = kv; }
        else             { g = vg; be = vb; mu = vm; va = vv; }
        float inv = g[c] / sqrtf(va[c] + 1e-5f);
        g_bnscale[i] = inv;
        g_bnbias[i]  = be[c] - mu[c] * inv;
    } else if (i < 4 * C_) {
        int c = i - 3 * C_;
        float inv = pg[c] / sqrtf(pv[c] + 1e-5f);
        g_pscale[c] = inv;
        g_pbias[c]  = pb[c] - pm[c] * inv + pbias[c] * inv;
    }
}

// ---------------- GEMM + BN affine -------------------------------------------
// Y[p][t,b,o,n] = (sum_c W_p[o,c] * X[t,b,c,n]) * scale[o_glob] + bias[o_glob]
// Columns flattened: j = t*6272 + b*196 + n, 25088 = 392*64. Rows: o_glob = by*128.
__global__ __launch_bounds__(256) void gemm_bn(
    const float* __restrict__ X, const float* __restrict__ w0,
    const float* __restrict__ w1, const float* __restrict__ w2,
    const float* __restrict__ scale, const float* __restrict__ bias,
    float* __restrict__ Y)
{
    __shared__ __align__(16) float Ws[8 * 132];
    __shared__ __align__(16) float Xs[8 * 64];
    __shared__ int sbase[64];

    int tid = threadIdx.x;
    int j0  = blockIdx.x * 64;
    int o0  = blockIdx.y * 128;
    int p   = o0 / C_;                      // which projection (tile never crosses 384)
    const float* w = (p == 0) ? w0 : ((p == 1) ? w1 : w2);
    int om0 = o0 - p * C_;

    if (tid < 64) {
        int j = j0 + tid;
        int t = j / (B_ * N_);
        int r = j - t * (B_ * N_);
        int b = r / N_;
        int n = r - b * N_;
        sbase[tid] = (t * B_ + b) * CN_ + n;
    }
    __syncthreads();

    float acc[8][4];
#pragma unroll
    for (int i = 0; i < 8; ++i)
#pragma unroll
        for (int j = 0; j < 4; ++j) acc[i][j] = 0.0f;

    int tx = tid & 15, ty = tid >> 4;

    for (int c0 = 0; c0 < C_; c0 += 8) {
        // load W tile: 128 rows x 8 k
        {
            int r  = tid >> 1;
            int kq = (tid & 1) * 4;
            float4 wv = *(const float4*)&w[(om0 + r) * C_ + c0 + kq];
            Ws[(kq + 0) * 132 + r] = wv.x;
            Ws[(kq + 1) * 132 + r] = wv.y;
            Ws[(kq + 2) * 132 + r] = wv.z;
            Ws[(kq + 3) * 132 + r] = wv.w;
        }
        // load X tile: 8 k x 64 j
#pragma unroll
        for (int u = 0; u < 2; ++u) {
            int idx = tid + u * 256;
            int kk = idx >> 6, jj = idx & 63;
            Xs[kk * 64 + jj] = X[sbase[jj] + (c0 + kk) * N_];
        }
        __syncthreads();
#pragma unroll
        for (int kk = 0; kk < 8; ++kk) {
            float4 a0 = *(const float4*)&Ws[kk * 132 + ty * 8];
            float4 a1 = *(const float4*)&Ws[kk * 132 + ty * 8 + 4];
            float4 bv = *(const float4*)&Xs[kk * 64 + tx * 4];
            float a[8] = {a0.x, a0.y, a0.z, a0.w, a1.x, a1.y, a1.z, a1.w};
            float b[4] = {bv.x, bv.y, bv.z, bv.w};
#pragma unroll
            for (int i = 0; i < 8; ++i)
#pragma unroll
                for (int j = 0; j < 4; ++j) acc[i][j] += a[i] * b[j];
        }
        __syncthreads();
    }

#pragma unroll
    for (int i = 0; i < 8; ++i) {
        int o  = o0 + ty * 8 + i;
        float sc = scale[o];
        float bi = bias[o];
        int om = o - p * C_;
#pragma unroll
        for (int j = 0; j < 4; ++j) {
            int jj = tx * 4 + j;
            Y[p * TBCN + sbase[jj] + om * N_] = acc[i][j] * sc + bi;
        }
    }
}

// ---------------- LIF (sequential over T, elementwise, float4) ---------------
// v=0; per t: v += (x - v)*0.5; s = (v >= thr); v = s ? 0 : v
__global__ void lif_kernel(const float* __restrict__ in, float* __restrict__ out,
                           float thr, int total4)
{
    int i = blockIdx.x * blockDim.x + threadIdx.x;
    if (i >= total4) return;
    const int q = BCN / 4;                 // 602112 float4 per plane-timestep
    int p = i / q;
    int r = i - p * q;
    const float4* ip = (const float4*)in + (size_t)p * (TBCN / 4) + r;
    float4*       op = (float4*)out      + (size_t)p * (TBCN / 4) + r;

    float4 v = make_float4(0.f, 0.f, 0.f, 0.f);
#pragma unroll
    for (int t = 0; t < T_; ++t) {
        float4 x = ip[(size_t)t * q];
        v.x += (x.x - v.x) * 0.5f;  v.y += (x.y - v.y) * 0.5f;
        v.z += (x.z - v.z) * 0.5f;  v.w += (x.w - v.w) * 0.5f;
        float4 s;
        s.x = (v.x >= thr) ? 1.0f : 0.0f;
        s.y = (v.y >= thr) ? 1.0f : 0.0f;
        s.z = (v.z >= thr) ? 1.0f : 0.0f;
        s.w = (v.w >= thr) ? 1.0f : 0.0f;
        op[(size_t)t * q] = s;
        if (s.x != 0.f) v.x = 0.f;
        if (s.y != 0.f) v.y = 0.f;
        if (s.z != 0.f) v.z = 0.f;
        if (s.w != 0.f) v.w = 0.f;
    }
}

// ---------------- Attention (per t,b,h): popcount QK^T, policy, AV -----------
__global__ __launch_bounds__(256) void attn_kernel(
    const float* __restrict__ qkv, const float* __restrict__ policy,
    float* __restrict__ out)
{
    __shared__ __align__(16) float s_v[N_ * 36];   // staging / v [n][d] / y staging
    __shared__ unsigned s_qm[N_], s_km[N_];
    __shared__ float s_pol[N_];

    int tid = threadIdx.x;
    int bz  = blockIdx.x;            // (t*B + b)*H + h
    int h   = bz % H_;
    int tb  = bz / H_;
    int base = tb * CN_ + h * D_ * N_;

    // --- stage q, build q masks ---
    for (int idx = tid; idx < D_ * N_; idx += 256) {
        int d = idx / N_, n = idx - d * N_;
        s_v[n * 36 + d] = qkv[base + d * N_ + n];
    }
    __syncthreads();
    int n = tid;
    if (n < N_) {
        unsigned m = 0;
#pragma unroll
        for (int d = 0; d < D_; ++d)
            if (s_v[n * 36 + d] != 0.0f) m |= (1u << d);
        s_qm[n] = m;
    }
    __syncthreads();
    // --- stage k, build k masks ---
    for (int idx = tid; idx < D_ * N_; idx += 256) {
        int d = idx / N_, nn = idx - d * N_;
        s_v[nn * 36 + d] = qkv[TBCN + base + d * N_ + nn];
    }
    __syncthreads();
    if (n < N_) {
        unsigned m = 0;
#pragma unroll
        for (int d = 0; d < D_; ++d)
            if (s_v[n * 36 + d] != 0.0f) m |= (1u << d);
        s_km[n] = m;
    }
    __syncthreads();
    // --- stage v (kept), policy ---
    for (int idx = tid; idx < D_ * N_; idx += 256) {
        int d = idx / N_, nn = idx - d * N_;
        s_v[nn * 36 + d] = qkv[2 * TBCN + base + d * N_ + nn];
    }
    if (tid < N_) s_pol[tid] = policy[tb * N_ + tid];
    __syncthreads();

    float y[D_];
    if (n < N_) {
#pragma unroll
        for (int d = 0; d < D_; ++d) y[d] = 0.0f;
        unsigned qm = s_qm[n];
        for (int m = 0; m < N_; ++m) {
            int cnt = __popc(qm & s_km[m]);
            if (cnt == 0) continue;
            float a = (float)cnt * ((m == n) ? 1.0f : s_pol[m]);
            const float4* vp = (const float4*)(s_v + m * 36);
#pragma unroll
            for (int q4 = 0; q4 < 8; ++q4) {
                float4 vv = vp[q4];
                y[4 * q4 + 0] += a * vv.x;
                y[4 * q4 + 1] += a * vv.y;
                y[4 * q4 + 2] += a * vv.z;
                y[4 * q4 + 3] += a * vv.w;
            }
        }
    }
    __syncthreads();   // everyone done reading s_v
    if (n < N_) {
#pragma unroll
        for (int d = 0; d < D_; ++d) s_v[d * N_ + n] = y[d] * 0.25f;
    }
    __syncthreads();
    for (int idx = tid; idx < D_ * N_; idx += 256) {
        int d = idx / N_, nn = idx - d * N_;
        out[base + d * N_ + nn] = s_v[idx];
    }
}

// ---------------- launch ------------------------------------------------------
extern "C" void kernel_launch(void* const* d_in, const int* in_sizes, int n_in,
                              void* d_out, int out_size)
{
    const float* x      = (const float*)d_in[0];
    const float* policy = (const float*)d_in[1];
    const float* qw = (const float*)d_in[2];
    const float* qg = (const float*)d_in[3];
    const float* qb = (const float*)d_in[4];
    const float* qm = (const float*)d_in[5];
    const float* qv = (const float*)d_in[6];
    const float* kw = (const float*)d_in[7];
    const float* kg = (const float*)d_in[8];
    const float* kb = (const float*)d_in[9];
    const float* km = (const float*)d_in[10];
    const float* kv = (const float*)d_in[11];
    const float* vw = (const float*)d_in[12];
    const float* vg = (const float*)d_in[13];
    const float* vb = (const float*)d_in[14];
    const float* vm = (const float*)d_in[15];
    const float* vv = (const float*)d_in[16];
    const float* pw = (const float*)d_in[17];
    const float* pg = (const float*)d_in[18];
    const float* pb = (const float*)d_in[19];
    const float* pm = (const float*)d_in[20];
    const float* pv = (const float*)d_in[21];
    const float* pbias = (const float*)d_in[22];

    float *qkv_p, *att_p, *bns_p, *bnb_p, *ps_p, *pbs_p;
    cudaGetSymbolAddress((void**)&qkv_p, g_qkv);
    cudaGetSymbolAddress((void**)&att_p, g_att);
    cudaGetSymbolAddress((void**)&bns_p, g_bnscale);
    cudaGetSymbolAddress((void**)&bnb_p, g_bnbias);
    cudaGetSymbolAddress((void**)&ps_p,  g_pscale);
    cudaGetSymbolAddress((void**)&pbs_p, g_pbias);

    setup_bn<<<6, 256>>>(qg, qb, qm, qv, kg, kb, km, kv, vg, vb, vm, vv,
                         pg, pb, pm, pv, pbias);

    // q,k,v conv+bn: [1152x384] @ [384x25088]
    gemm_bn<<<dim3(TOKS / 64, 9), 256>>>(x, qw, kw, vw, bns_p, bnb_p, qkv_p);

    // LIF(theta=1) over q,k,v in place
    lif_kernel<<<(3 * BCN / 4 + 255) / 256, 256>>>(qkv_p, qkv_p, 1.0f, 3 * BCN / 4);

    // attention per (t,b,h)
    attn_kernel<<<T_ * B_ * H_, 256>>>(qkv_p, policy, att_p);

    // LIF(theta=0.5) in place
    lif_kernel<<<(BCN / 4 + 255) / 256, 256>>>(att_p, att_p, 0.5f, BCN / 4);

    // proj conv+bias+bn: [384x384] @ [384x25088] -> reuse g_qkv plane 0
    gemm_bn<<<dim3(TOKS / 64, 3), 256>>>(att_p, pw, pw, pw, ps_p, pbs_p, qkv_p);

    // final LIF(theta=1) -> d_out
    lif_kernel<<<(BCN / 4 + 255) / 256, 256>>>(qkv_p, (float*)d_out, 1.0f, BCN / 4);
}